// round 15
// baseline (speedup 1.0000x reference)
#include <cuda_runtime.h>

#define NN 1500
#define DD 64
#define ATT_STRIDE 1536
#define TOPK 16
#define CAP2 512    // candidate buffer (u64) for threshold filter
#define TRB2 48     // transpose blocks appended to k_encode grid (48*256 = 12288)

typedef unsigned long long u64;

// ---------------- scratch (device globals; no allocation allowed) ----------
__device__ float g_h[NN * DD];
__device__ float g_pi[NN * DD];
__device__ float g_pjb[NN * DD];     // pj + att_b1 folded in
__device__ float g_msgpos[NN * DD];
__device__ float g_msgneg[NN * DD];
__device__ float g_att[NN * ATT_STRIDE];
// transposed GRU weights: [f][gate*64 + d]  (192 per f-row)
__device__ float g_wTip[64 * 192];
__device__ float g_wThp[64 * 192];
__device__ float g_wTin[64 * 192];
__device__ float g_wThn[64 * 192];

__device__ __forceinline__ float sigmoid_fast(float x) {
    return 1.0f / (1.0f + __expf(-x));
}
__device__ __forceinline__ float sigmoidf_(float x) {
    return 1.0f / (1.0f + expf(-x));
}

// ascending-by-lane bitonic sort of 32 u64 (one per lane)
__device__ __forceinline__ u64 bitonic32_asc(u64 v, int lane)
{
#pragma unroll
    for (int k = 2; k <= 32; k <<= 1) {
#pragma unroll
        for (int j = k >> 1; j > 0; j >>= 1) {
            u64 o = __shfl_xor_sync(0xffffffffu, v, j);
            bool up = ((lane & k) == 0);
            bool lo = ((lane & j) == 0);
            u64 mn = (v < o) ? v : o;
            u64 mx = (v < o) ? o : v;
            v = (up == lo) ? mn : mx;
        }
    }
    return v;
}

// ---------------- kernel 1: encoder + LN + ReLU + 4 projections ------------
// grid = NN + TRB2 blocks, 256 threads. One node per block; the 4 thread-
// groups (64 threads each) redundantly compute h0+LN (bit-identical), then
// each group computes ONE projection. Blocks >= NN transpose GRU weights.
__global__ void __launch_bounds__(256)
k_encode(const float* __restrict__ x_risk,
         const float* __restrict__ enc_w, const float* __restrict__ enc_b,
         const float* __restrict__ ln_g, const float* __restrict__ ln_b,
         const float* __restrict__ att_w1, const float* __restrict__ att_b1,
         const float* __restrict__ msg_pos_w, const float* __restrict__ msg_pos_b,
         const float* __restrict__ msg_neg_w, const float* __restrict__ msg_neg_b,
         const float* __restrict__ wih_p, const float* __restrict__ whh_p,
         const float* __restrict__ wih_n, const float* __restrict__ whh_n)
{
    int i = blockIdx.x;
    int tid = threadIdx.x;

    if (i >= NN) {
        // transpose role: out[f*192 + row] = in[row*64 + f]
        int o = (i - NN) * 256 + tid;
        int row = o % 192, f = o / 192;
        int src = row * 64 + f;
        g_wTip[o] = wih_p[src];
        g_wThp[o] = whh_p[src];
        g_wTin[o] = wih_n[src];
        g_wThn[o] = whh_n[src];
        return;
    }

    int d = tid & 63;
    int grp = tid >> 6;     // 0..3
    int warp = tid >> 5;    // 0..7
    int lane = tid & 31;

    __shared__ float s_x[DD];
    __shared__ float s_h[DD];
    __shared__ float s_sum[8];
    __shared__ float s_sq[8];

    if (tid < DD)
        s_x[tid] = x_risk[(size_t)7 * NN * DD + (size_t)i * DD + tid];
    __syncthreads();

    // redundant h0 across groups (identical sequence -> bit-identical)
    float h0 = enc_b[d];
#pragma unroll
    for (int f = 0; f < DD; f++) h0 = fmaf(s_x[f], enc_w[f * DD + d], h0);

    // fused sum + sumsq reduction within each group's 2 warps
    float vs = h0;
    float vq = h0 * h0;
#pragma unroll
    for (int o = 16; o > 0; o >>= 1) {
        vs += __shfl_xor_sync(0xffffffffu, vs, o);
        vq += __shfl_xor_sync(0xffffffffu, vq, o);
    }
    if (lane == 0) { s_sum[warp] = vs; s_sq[warp] = vq; }
    __syncthreads();
    float mu = (s_sum[2 * grp] + s_sum[2 * grp + 1]) * (1.0f / DD);
    float ex2 = (s_sq[2 * grp] + s_sq[2 * grp + 1]) * (1.0f / DD);
    float var = ex2 - mu * mu;
    float c = h0 - mu;

    float hv = fmaxf(c * rsqrtf(var + 1e-5f) * ln_g[d] + ln_b[d], 0.0f);
    if (grp == 0) {
        s_h[d] = hv;
        g_h[(size_t)i * DD + d] = hv;
    }
    __syncthreads();

    // one projection per group
    const float* W = (grp == 0) ? att_w1
                   : (grp == 1) ? (att_w1 + DD * DD)
                   : (grp == 2) ? msg_pos_w : msg_neg_w;
    float acc = (grp == 0) ? 0.0f
              : (grp == 1) ? att_b1[d]
              : (grp == 2) ? msg_pos_b[d] : msg_neg_b[d];
#pragma unroll
    for (int k = 0; k < DD; k++)
        acc = fmaf(s_h[k], W[k * DD + d], acc);

    float* dst = (grp == 0) ? g_pi : (grp == 1) ? g_pjb
               : (grp == 2) ? g_msgpos : g_msgneg;
    dst[(size_t)i * DD + d] = acc;
}

// ---------------- kernel 2: pairwise attention scores (R7 proven form) -----
__global__ void k_att(const float* __restrict__ att_w2, const float* __restrict__ att_b2)
{
    __shared__ float sp_i[64][65];
    __shared__ float sp_j[64][65];
    __shared__ float s_w2[64];

    int i0 = blockIdx.y * 64;
    int j0 = blockIdx.x * 64;
    int tid = threadIdx.y * 16 + threadIdx.x;

    for (int t = tid; t < 64 * 16; t += 256) {
        int r = t >> 4, c4 = t & 15;
        int gi = i0 + r;
        float4 a = (gi < NN) ? __ldg((const float4*)(g_pi + (size_t)gi * DD) + c4)
                             : make_float4(0.f, 0.f, 0.f, 0.f);
        sp_i[r][c4 * 4 + 0] = a.x; sp_i[r][c4 * 4 + 1] = a.y;
        sp_i[r][c4 * 4 + 2] = a.z; sp_i[r][c4 * 4 + 3] = a.w;
        int gj = j0 + r;
        float4 b = (gj < NN) ? __ldg((const float4*)(g_pjb + (size_t)gj * DD) + c4)
                             : make_float4(0.f, 0.f, 0.f, 0.f);
        sp_j[r][c4 * 4 + 0] = b.x; sp_j[r][c4 * 4 + 1] = b.y;
        sp_j[r][c4 * 4 + 2] = b.z; sp_j[r][c4 * 4 + 3] = b.w;
    }
    if (tid < 64) s_w2[tid] = att_w2[tid];
    __syncthreads();

    int ri0 = threadIdx.y * 4;
    int rj0 = threadIdx.x * 4;
    float acc[4][4] = {};
#pragma unroll 8
    for (int dd = 0; dd < 64; dd++) {
        float w = s_w2[dd];
        float av[4] = {sp_i[ri0 + 0][dd], sp_i[ri0 + 1][dd], sp_i[ri0 + 2][dd], sp_i[ri0 + 3][dd]};
        float bv[4] = {sp_j[rj0 + 0][dd], sp_j[rj0 + 1][dd], sp_j[rj0 + 2][dd], sp_j[rj0 + 3][dd]};
#pragma unroll
        for (int ri = 0; ri < 4; ri++)
#pragma unroll
            for (int rj = 0; rj < 4; rj++) {
                float t = fmaxf(av[ri] + bv[rj], 0.0f);
                acc[ri][rj] = fmaf(t, w, acc[ri][rj]);
            }
    }
    float bias2 = att_b2[0];
#pragma unroll
    for (int ri = 0; ri < 4; ri++) {
#pragma unroll
        for (int rj = 0; rj < 4; rj++) {
            int gi = i0 + ri0 + ri;
            int gj = j0 + rj0 + rj;
            if (gi < NN && gj < NN) {
                float s = (gi == gj) ? 0.0f : sigmoid_fast(acc[ri][rj] + bias2);
                g_att[(size_t)gi * ATT_STRIDE + gj] = s;
            }
        }
    }
}

// ---------------- kernel 3: top-16 + aggregation + dual GRU + combine ------
// grid = NN blocks, 256 threads. One node per block, fully fused tail.
__global__ void k_topk_gru(const float* __restrict__ G,
                           const float* __restrict__ bih_p, const float* __restrict__ bhh_p,
                           const float* __restrict__ bih_n, const float* __restrict__ bhh_n,
                           const float* __restrict__ comb_w, const float* __restrict__ comb_b,
                           float* __restrict__ out)
{
    int i = blockIdx.x;
    int tid = threadIdx.x;
    int lane = tid & 31, w = tid >> 5;

    __shared__ u64 s_seed[32];
    __shared__ u64 s_cand[CAP2];
    __shared__ u64 s_T0;
    __shared__ int   s_cnt;
    __shared__ int   s_topi[TOPK];
    __shared__ float s_wpos[TOPK];
    __shared__ float s_wneg[TOPK];
    __shared__ float s_inv[2];
    __shared__ float s_mpos[DD], s_mneg[DD], s_hh[DD];
    __shared__ float s_gp[6][DD];   // pos: ir iz in hr hz hn
    __shared__ float s_gn[6][DD];   // neg
    __shared__ float s_hp[DD], s_hn[DD];

    if (tid == 0) s_cnt = 0;

    // ---- top-16 selection (proven path) ----
    u64 key[6];
#pragma unroll
    for (int it = 0; it < 6; it++) {
        int j = tid + it * 256;
        if (j < NN) {
            float v = g_att[(size_t)i * ATT_STRIDE + j];
            key[it] = (((u64)__float_as_uint(v)) << 32) | (unsigned)(4095 - j);
        } else {
            key[it] = 0ull;
        }
    }

    u64 tmax = key[0];
#pragma unroll
    for (int it = 1; it < 6; it++) tmax = (key[it] > tmax) ? key[it] : tmax;
    u64 srt = bitonic32_asc(tmax, lane);
    if (lane >= 28) s_seed[w * 4 + (lane - 28)] = srt;
    __syncthreads();

    if (w == 0) {
        u64 c = bitonic32_asc(s_seed[lane], lane);
        if (lane == 16) s_T0 = c;
    }
    __syncthreads();
    u64 T0 = s_T0;

    {
        unsigned bal[6];
        int wtot = 0;
#pragma unroll
        for (int it = 0; it < 6; it++) {
            bal[it] = __ballot_sync(0xffffffffu, key[it] >= T0);
            wtot += __popc(bal[it]);
        }
        int base = 0;
        if (lane == 0) base = atomicAdd(&s_cnt, wtot);
        base = __shfl_sync(0xffffffffu, base, 0);
        unsigned lt = (1u << lane) - 1u;
        int off = 0;
#pragma unroll
        for (int it = 0; it < 6; it++) {
            if (key[it] >= T0) {
                int p = base + off + __popc(bal[it] & lt);
                if (p < CAP2) s_cand[p] = key[it];
            }
            off += __popc(bal[it]);
        }
    }
    __syncthreads();
    int m = s_cnt;

    if (m <= 32) {
        if (w == 0) {
            u64 c = (lane < m) ? s_cand[lane] : 0ull;
            c = bitonic32_asc(c, lane);
            if (lane >= 16) {
                int t = 31 - lane;
                s_topi[t] = 4095 - (int)(c & 0xffffffffu);
                s_wpos[t] = __uint_as_float((unsigned)(c >> 32));
            }
        }
    } else if (m <= 128) {
        if (w == 0) {
            u64 c[4];
#pragma unroll
            for (int q = 0; q < 4; q++) {
                int p = lane + q * 32;
                c[q] = (p < m) ? s_cand[p] : 0ull;
            }
            for (int t = 0; t < TOPK; t++) {
                u64 mx = c[0];
#pragma unroll
                for (int q = 1; q < 4; q++) mx = (c[q] > mx) ? c[q] : mx;
#pragma unroll
                for (int o = 16; o > 0; o >>= 1) {
                    u64 other = __shfl_xor_sync(0xffffffffu, mx, o);
                    mx = (other > mx) ? other : mx;
                }
                if (lane == 0) {
                    s_topi[t] = 4095 - (int)(mx & 0xffffffffu);
                    s_wpos[t] = __uint_as_float((unsigned)(mx >> 32));
                }
#pragma unroll
                for (int q = 0; q < 4; q++) if (c[q] == mx) c[q] = 0ull;
            }
        }
    } else {
        __shared__ u64 s_fb[128];
        for (int t = 0; t < TOPK; t++) {
            u64 mx = key[0];
#pragma unroll
            for (int it = 1; it < 6; it++) mx = (key[it] > mx) ? key[it] : mx;
#pragma unroll
            for (int o = 16; o > 0; o >>= 1) {
                u64 other = __shfl_xor_sync(0xffffffffu, mx, o);
                mx = (other > mx) ? other : mx;
            }
            if (lane == 0) s_fb[w * TOPK + t] = mx;
#pragma unroll
            for (int it = 0; it < 6; it++) if (key[it] == mx) key[it] = 0ull;
        }
        __syncthreads();
        if (w == 0) {
            u64 c[4];
#pragma unroll
            for (int q = 0; q < 4; q++) c[q] = s_fb[lane + q * 32];
            for (int t = 0; t < TOPK; t++) {
                u64 mx = c[0];
#pragma unroll
                for (int q = 1; q < 4; q++) mx = (c[q] > mx) ? c[q] : mx;
#pragma unroll
                for (int o = 16; o > 0; o >>= 1) {
                    u64 other = __shfl_xor_sync(0xffffffffu, mx, o);
                    mx = (other > mx) ? other : mx;
                }
                if (lane == 0) {
                    s_topi[t] = 4095 - (int)(mx & 0xffffffffu);
                    s_wpos[t] = __uint_as_float((unsigned)(mx >> 32));
                }
#pragma unroll
                for (int q = 0; q < 4; q++) if (c[q] == mx) c[q] = 0ull;
            }
        }
    }
    __syncthreads();

    if (tid < TOPK) {
        int j = s_topi[tid];
        float a = s_wpos[tid];
        float g = G[(size_t)i * NN + j];
        s_wpos[tid] = (g > 0.3f) ? a : 0.0f;
        s_wneg[tid] = (g < -0.3f) ? a : 0.0f;
    }
    __syncthreads();
    if (tid == 0) {
        float sp = 0.f, sn = 0.f;
#pragma unroll
        for (int t = 0; t < TOPK; t++) { sp += s_wpos[t]; sn += s_wneg[t]; }
        s_inv[0] = 1.0f / (sp + 1e-8f);
        s_inv[1] = 1.0f / (sn + 1e-8f);
    }
    __syncthreads();

    // ---- message aggregation into smem (+ load h) ----
    if (tid < 64) {
        int d = tid;
        float acc = 0.f;
#pragma unroll
        for (int t = 0; t < TOPK; t++)
            acc = fmaf(s_wpos[t], g_msgpos[(size_t)s_topi[t] * DD + d], acc);
        s_mpos[d] = acc * s_inv[0];
    } else if (tid < 128) {
        int d = tid - 64;
        float acc = 0.f;
#pragma unroll
        for (int t = 0; t < TOPK; t++)
            acc = fmaf(s_wneg[t], g_msgneg[(size_t)s_topi[t] * DD + d], acc);
        s_mneg[d] = acc * s_inv[1];
    } else if (tid < 192) {
        int d = tid - 128;
        s_hh[d] = g_h[(size_t)i * DD + d];
    }
    __syncthreads();

    // ---- GRU gate dot-products: 4 groups x 64 d, transposed weights ----
    {
        int d = tid & 63;
        int grp = tid >> 6;
        float a0 = 0.f, a1 = 0.f, a2 = 0.f;
        const float* wT = (grp == 0) ? g_wTip : (grp == 1) ? g_wThp
                        : (grp == 2) ? g_wTin : g_wThn;
        const float* vec = (grp == 0) ? s_mpos : (grp == 1) ? s_hh
                         : (grp == 2) ? s_mneg : s_hh;
#pragma unroll 8
        for (int f = 0; f < DD; f++) {
            float xv = vec[f];
            const float* wr = wT + f * 192;
            a0 = fmaf(xv, wr[d], a0);
            a1 = fmaf(xv, wr[64 + d], a1);
            a2 = fmaf(xv, wr[128 + d], a2);
        }
        float* dst = (grp == 0) ? &s_gp[0][0] : (grp == 1) ? &s_gp[3][0]
                   : (grp == 2) ? &s_gn[0][0] : &s_gn[3][0];
        dst[0 * DD + d] = a0;
        dst[1 * DD + d] = a1;
        dst[2 * DD + d] = a2;
    }
    __syncthreads();

    // ---- GRU nonlinearities ----
    if (tid < 64) {
        int d = tid;
        float r = sigmoidf_((s_gp[0][d] + bih_p[d]) + (s_gp[3][d] + bhh_p[d]));
        float z = sigmoidf_((s_gp[1][d] + bih_p[64 + d]) + (s_gp[4][d] + bhh_p[64 + d]));
        float n2 = tanhf((s_gp[2][d] + bih_p[128 + d]) + r * (s_gp[5][d] + bhh_p[128 + d]));
        s_hp[d] = (1.0f - z) * n2 + z * s_hh[d];
    } else if (tid < 128) {
        int d = tid - 64;
        float r = sigmoidf_((s_gn[0][d] + bih_n[d]) + (s_gn[3][d] + bhh_n[d]));
        float z = sigmoidf_((s_gn[1][d] + bih_n[64 + d]) + (s_gn[4][d] + bhh_n[64 + d]));
        float n2 = tanhf((s_gn[2][d] + bih_n[128 + d]) + r * (s_gn[5][d] + bhh_n[128 + d]));
        s_hn[d] = (1.0f - z) * n2 + z * s_hh[d];
    }
    __syncthreads();

    // ---- combine: out = [h_pos, h_neg] @ comb_w + comb_b ----
    if (tid < 64) {
        int d = tid;
        float acc = comb_b[d];
#pragma unroll 8
        for (int kk = 0; kk < DD; kk++) {
            acc = fmaf(s_hp[kk], comb_w[kk * DD + d], acc);
            acc = fmaf(s_hn[kk], comb_w[(DD + kk) * DD + d], acc);
        }
        out[(size_t)i * DD + d] = acc;
    }
}

// ---------------- launch ---------------------------------------------------
extern "C" void kernel_launch(void* const* d_in, const int* in_sizes, int n_in,
                              void* d_out, int out_size)
{
    const float* x_risk   = (const float*)d_in[0];
    const float* mfg      = (const float*)d_in[1];
    const float* enc_w    = (const float*)d_in[2];
    const float* enc_b    = (const float*)d_in[3];
    const float* ln_g     = (const float*)d_in[4];
    const float* ln_b     = (const float*)d_in[5];
    const float* att_w1   = (const float*)d_in[6];
    const float* att_b1   = (const float*)d_in[7];
    const float* att_w2   = (const float*)d_in[8];
    const float* att_b2   = (const float*)d_in[9];
    const float* msg_pos_w = (const float*)d_in[10];
    const float* msg_pos_b = (const float*)d_in[11];
    const float* gru_pos_wih = (const float*)d_in[12];
    const float* gru_pos_whh = (const float*)d_in[13];
    const float* gru_pos_bih = (const float*)d_in[14];
    const float* gru_pos_bhh = (const float*)d_in[15];
    const float* msg_neg_w = (const float*)d_in[16];
    const float* msg_neg_b = (const float*)d_in[17];
    const float* gru_neg_wih = (const float*)d_in[18];
    const float* gru_neg_whh = (const float*)d_in[19];
    const float* gru_neg_bih = (const float*)d_in[20];
    const float* gru_neg_bhh = (const float*)d_in[21];
    const float* comb_w   = (const float*)d_in[22];
    const float* comb_b   = (const float*)d_in[23];
    float* out = (float*)d_out;

    // encode (blocks 0..NN-1) + GRU-weight transpose (blocks NN..NN+TRB2-1)
    k_encode<<<NN + TRB2, 256>>>(x_risk, enc_w, enc_b, ln_g, ln_b,
                                 att_w1, att_b1, msg_pos_w, msg_pos_b,
                                 msg_neg_w, msg_neg_b,
                                 gru_pos_wih, gru_pos_whh,
                                 gru_neg_wih, gru_neg_whh);

    dim3 gb((NN + 63) / 64, (NN + 63) / 64);
    dim3 tb(16, 16);
    k_att<<<gb, tb>>>(att_w2, att_b2);

    k_topk_gru<<<NN, 256>>>(mfg,
                            gru_pos_bih, gru_pos_bhh,
                            gru_neg_bih, gru_neg_bhh,
                            comb_w, comb_b, out);
}

// round 16
// speedup vs baseline: 1.0675x; 1.0675x over previous
#include <cuda_runtime.h>

#define NN 1500
#define DD 64
#define ATT_STRIDE 1536
#define TOPK 16
#define CAP2 512    // candidate buffer (u64) for threshold filter
#define TRB 192     // transpose blocks appended to k_encode grid (192*64 = 12288)

typedef unsigned long long u64;

// ---------------- scratch (device globals; no allocation allowed) ----------
__device__ float g_h[NN * DD];
__device__ float g_pi[NN * DD];
__device__ float g_pjb[NN * DD];     // pj + att_b1 folded in
__device__ float g_msgpos[NN * DD];
__device__ float g_msgneg[NN * DD];
__device__ float g_att[NN * ATT_STRIDE];
// transposed GRU weights: [f][gate*64 + d]  (192 per f-row)
__device__ float g_wTip[64 * 192];
__device__ float g_wThp[64 * 192];
__device__ float g_wTin[64 * 192];
__device__ float g_wThn[64 * 192];

__device__ __forceinline__ float sigmoid_fast(float x) {
    return 1.0f / (1.0f + __expf(-x));
}
__device__ __forceinline__ float sigmoidf_(float x) {
    return 1.0f / (1.0f + expf(-x));
}

// ascending-by-lane bitonic sort of 32 u64 (one per lane)
__device__ __forceinline__ u64 bitonic32_asc(u64 v, int lane)
{
#pragma unroll
    for (int k = 2; k <= 32; k <<= 1) {
#pragma unroll
        for (int j = k >> 1; j > 0; j >>= 1) {
            u64 o = __shfl_xor_sync(0xffffffffu, v, j);
            bool up = ((lane & k) == 0);
            bool lo = ((lane & j) == 0);
            u64 mn = (v < o) ? v : o;
            u64 mx = (v < o) ? o : v;
            v = (up == lo) ? mn : mx;
        }
    }
    return v;
}

// ---------------- kernel 1: encoder + LN + ReLU + 4 projections ------------
// grid = NN + TRB blocks, 64 threads. Blocks >= NN transpose the GRU weights.
// (exact R12 form - empirical wall optimum)
__global__ void k_encode(const float* __restrict__ x_risk,
                         const float* __restrict__ enc_w, const float* __restrict__ enc_b,
                         const float* __restrict__ ln_g, const float* __restrict__ ln_b,
                         const float* __restrict__ att_w1, const float* __restrict__ att_b1,
                         const float* __restrict__ msg_pos_w, const float* __restrict__ msg_pos_b,
                         const float* __restrict__ msg_neg_w, const float* __restrict__ msg_neg_b,
                         const float* __restrict__ wih_p, const float* __restrict__ whh_p,
                         const float* __restrict__ wih_n, const float* __restrict__ whh_n)
{
    int i = blockIdx.x;
    int d = threadIdx.x;  // 0..63

    if (i >= NN) {
        int o = (i - NN) * 64 + d;
        int row = o % 192, f = o / 192;
        int src = row * 64 + f;
        g_wTip[o] = wih_p[src];
        g_wThp[o] = whh_p[src];
        g_wTin[o] = wih_n[src];
        g_wThn[o] = whh_n[src];
        return;
    }

    __shared__ float s_x[DD];
    __shared__ float s_h[DD];
    __shared__ float s_red[2];

    const float* x = x_risk + (size_t)7 * NN * DD + (size_t)i * DD;
    s_x[d] = x[d];
    __syncthreads();

    float h0 = enc_b[d];
#pragma unroll
    for (int f = 0; f < DD; f++) h0 = fmaf(s_x[f], enc_w[f * DD + d], h0);

    float v = h0;
#pragma unroll
    for (int o = 16; o > 0; o >>= 1) v += __shfl_xor_sync(0xffffffffu, v, o);
    if ((d & 31) == 0) s_red[d >> 5] = v;
    __syncthreads();
    float mu = (s_red[0] + s_red[1]) * (1.0f / DD);
    __syncthreads();
    float c = h0 - mu;
    v = c * c;
#pragma unroll
    for (int o = 16; o > 0; o >>= 1) v += __shfl_xor_sync(0xffffffffu, v, o);
    if ((d & 31) == 0) s_red[d >> 5] = v;
    __syncthreads();
    float var = (s_red[0] + s_red[1]) * (1.0f / DD);

    float hv = c * rsqrtf(var + 1e-5f) * ln_g[d] + ln_b[d];
    hv = fmaxf(hv, 0.0f);
    s_h[d] = hv;
    g_h[i * DD + d] = hv;
    __syncthreads();

    float pi_ = 0.0f;
    float pj_ = att_b1[d];
    float mp = msg_pos_b[d];
    float mn = msg_neg_b[d];
#pragma unroll
    for (int k = 0; k < DD; k++) {
        float hk = s_h[k];
        pi_ = fmaf(hk, att_w1[k * DD + d], pi_);
        pj_ = fmaf(hk, att_w1[(DD + k) * DD + d], pj_);
        mp  = fmaf(hk, msg_pos_w[k * DD + d], mp);
        mn  = fmaf(hk, msg_neg_w[k * DD + d], mn);
    }
    g_pi[i * DD + d] = pi_;
    g_pjb[i * DD + d] = pj_;
    g_msgpos[i * DD + d] = mp;
    g_msgneg[i * DD + d] = mn;
}

// ---------------- kernel 2: pairwise attention scores (float4 stores) ------
// R7 compute form; stores vectorized: g_att rows padded to 1536, columns
// >= NN are never read by k_topk_gru, so unconditional float4 writes are safe.
__global__ void k_att(const float* __restrict__ att_w2, const float* __restrict__ att_b2)
{
    __shared__ float sp_i[64][65];
    __shared__ float sp_j[64][65];
    __shared__ float s_w2[64];

    int i0 = blockIdx.y * 64;
    int j0 = blockIdx.x * 64;
    int tid = threadIdx.y * 16 + threadIdx.x;

    for (int t = tid; t < 64 * 16; t += 256) {
        int r = t >> 4, c4 = t & 15;
        int gi = i0 + r;
        float4 a = (gi < NN) ? __ldg((const float4*)(g_pi + (size_t)gi * DD) + c4)
                             : make_float4(0.f, 0.f, 0.f, 0.f);
        sp_i[r][c4 * 4 + 0] = a.x; sp_i[r][c4 * 4 + 1] = a.y;
        sp_i[r][c4 * 4 + 2] = a.z; sp_i[r][c4 * 4 + 3] = a.w;
        int gj = j0 + r;
        float4 b = (gj < NN) ? __ldg((const float4*)(g_pjb + (size_t)gj * DD) + c4)
                             : make_float4(0.f, 0.f, 0.f, 0.f);
        sp_j[r][c4 * 4 + 0] = b.x; sp_j[r][c4 * 4 + 1] = b.y;
        sp_j[r][c4 * 4 + 2] = b.z; sp_j[r][c4 * 4 + 3] = b.w;
    }
    if (tid < 64) s_w2[tid] = att_w2[tid];
    __syncthreads();

    int ri0 = threadIdx.y * 4;
    int rj0 = threadIdx.x * 4;
    float acc[4][4] = {};
#pragma unroll 8
    for (int dd = 0; dd < 64; dd++) {
        float w = s_w2[dd];
        float av[4] = {sp_i[ri0 + 0][dd], sp_i[ri0 + 1][dd], sp_i[ri0 + 2][dd], sp_i[ri0 + 3][dd]};
        float bv[4] = {sp_j[rj0 + 0][dd], sp_j[rj0 + 1][dd], sp_j[rj0 + 2][dd], sp_j[rj0 + 3][dd]};
#pragma unroll
        for (int ri = 0; ri < 4; ri++)
#pragma unroll
            for (int rj = 0; rj < 4; rj++) {
                float t = fmaxf(av[ri] + bv[rj], 0.0f);
                acc[ri][rj] = fmaf(t, w, acc[ri][rj]);
            }
    }
    float bias2 = att_b2[0];
#pragma unroll
    for (int ri = 0; ri < 4; ri++) {
        int gi = i0 + ri0 + ri;
        if (gi < NN) {
            int gj0 = j0 + rj0;
            float4 o;
            o.x = (gi == gj0 + 0) ? 0.0f : sigmoid_fast(acc[ri][0] + bias2);
            o.y = (gi == gj0 + 1) ? 0.0f : sigmoid_fast(acc[ri][1] + bias2);
            o.z = (gi == gj0 + 2) ? 0.0f : sigmoid_fast(acc[ri][2] + bias2);
            o.w = (gi == gj0 + 3) ? 0.0f : sigmoid_fast(acc[ri][3] + bias2);
            *(float4*)(g_att + (size_t)gi * ATT_STRIDE + gj0) = o;
        }
    }
}

// ---------------- kernel 3: top-16 + aggregation + dual GRU + combine ------
// grid = NN blocks, 256 threads. One node per block, fully fused tail.
__global__ void k_topk_gru(const float* __restrict__ G,
                           const float* __restrict__ bih_p, const float* __restrict__ bhh_p,
                           const float* __restrict__ bih_n, const float* __restrict__ bhh_n,
                           const float* __restrict__ comb_w, const float* __restrict__ comb_b,
                           float* __restrict__ out)
{
    int i = blockIdx.x;
    int tid = threadIdx.x;
    int lane = tid & 31, w = tid >> 5;

    __shared__ u64 s_seed[32];
    __shared__ u64 s_cand[CAP2];
    __shared__ u64 s_T0;
    __shared__ int   s_cnt;
    __shared__ int   s_topi[TOPK];
    __shared__ float s_wpos[TOPK];
    __shared__ float s_wneg[TOPK];
    __shared__ float s_inv[2];
    __shared__ float s_mpos[DD], s_mneg[DD], s_hh[DD];
    __shared__ float s_gp[6][DD];   // pos: ir iz in hr hz hn
    __shared__ float s_gn[6][DD];   // neg
    __shared__ float s_hp[DD], s_hn[DD];

    if (tid == 0) s_cnt = 0;

    // ---- top-16 selection (proven path) ----
    u64 key[6];
#pragma unroll
    for (int it = 0; it < 6; it++) {
        int j = tid + it * 256;
        if (j < NN) {
            float v = g_att[(size_t)i * ATT_STRIDE + j];
            key[it] = (((u64)__float_as_uint(v)) << 32) | (unsigned)(4095 - j);
        } else {
            key[it] = 0ull;
        }
    }

    u64 tmax = key[0];
#pragma unroll
    for (int it = 1; it < 6; it++) tmax = (key[it] > tmax) ? key[it] : tmax;
    u64 srt = bitonic32_asc(tmax, lane);
    if (lane >= 28) s_seed[w * 4 + (lane - 28)] = srt;
    __syncthreads();

    if (w == 0) {
        u64 c = bitonic32_asc(s_seed[lane], lane);
        if (lane == 16) s_T0 = c;
    }
    __syncthreads();
    u64 T0 = s_T0;

    {
        unsigned bal[6];
        int wtot = 0;
#pragma unroll
        for (int it = 0; it < 6; it++) {
            bal[it] = __ballot_sync(0xffffffffu, key[it] >= T0);
            wtot += __popc(bal[it]);
        }
        int base = 0;
        if (lane == 0) base = atomicAdd(&s_cnt, wtot);
        base = __shfl_sync(0xffffffffu, base, 0);
        unsigned lt = (1u << lane) - 1u;
        int off = 0;
#pragma unroll
        for (int it = 0; it < 6; it++) {
            if (key[it] >= T0) {
                int p = base + off + __popc(bal[it] & lt);
                if (p < CAP2) s_cand[p] = key[it];
            }
            off += __popc(bal[it]);
        }
    }
    __syncthreads();
    int m = s_cnt;

    if (m <= 32) {
        if (w == 0) {
            u64 c = (lane < m) ? s_cand[lane] : 0ull;
            c = bitonic32_asc(c, lane);
            if (lane >= 16) {
                int t = 31 - lane;
                s_topi[t] = 4095 - (int)(c & 0xffffffffu);
                s_wpos[t] = __uint_as_float((unsigned)(c >> 32));
            }
        }
    } else if (m <= 128) {
        if (w == 0) {
            u64 c[4];
#pragma unroll
            for (int q = 0; q < 4; q++) {
                int p = lane + q * 32;
                c[q] = (p < m) ? s_cand[p] : 0ull;
            }
            for (int t = 0; t < TOPK; t++) {
                u64 mx = c[0];
#pragma unroll
                for (int q = 1; q < 4; q++) mx = (c[q] > mx) ? c[q] : mx;
#pragma unroll
                for (int o = 16; o > 0; o >>= 1) {
                    u64 other = __shfl_xor_sync(0xffffffffu, mx, o);
                    mx = (other > mx) ? other : mx;
                }
                if (lane == 0) {
                    s_topi[t] = 4095 - (int)(mx & 0xffffffffu);
                    s_wpos[t] = __uint_as_float((unsigned)(mx >> 32));
                }
#pragma unroll
                for (int q = 0; q < 4; q++) if (c[q] == mx) c[q] = 0ull;
            }
        }
    } else {
        __shared__ u64 s_fb[128];
        for (int t = 0; t < TOPK; t++) {
            u64 mx = key[0];
#pragma unroll
            for (int it = 1; it < 6; it++) mx = (key[it] > mx) ? key[it] : mx;
#pragma unroll
            for (int o = 16; o > 0; o >>= 1) {
                u64 other = __shfl_xor_sync(0xffffffffu, mx, o);
                mx = (other > mx) ? other : mx;
            }
            if (lane == 0) s_fb[w * TOPK + t] = mx;
#pragma unroll
            for (int it = 0; it < 6; it++) if (key[it] == mx) key[it] = 0ull;
        }
        __syncthreads();
        if (w == 0) {
            u64 c[4];
#pragma unroll
            for (int q = 0; q < 4; q++) c[q] = s_fb[lane + q * 32];
            for (int t = 0; t < TOPK; t++) {
                u64 mx = c[0];
#pragma unroll
                for (int q = 1; q < 4; q++) mx = (c[q] > mx) ? c[q] : mx;
#pragma unroll
                for (int o = 16; o > 0; o >>= 1) {
                    u64 other = __shfl_xor_sync(0xffffffffu, mx, o);
                    mx = (other > mx) ? other : mx;
                }
                if (lane == 0) {
                    s_topi[t] = 4095 - (int)(mx & 0xffffffffu);
                    s_wpos[t] = __uint_as_float((unsigned)(mx >> 32));
                }
#pragma unroll
                for (int q = 0; q < 4; q++) if (c[q] == mx) c[q] = 0ull;
            }
        }
    }
    __syncthreads();

    if (tid < TOPK) {
        int j = s_topi[tid];
        float a = s_wpos[tid];
        float g = G[(size_t)i * NN + j];
        s_wpos[tid] = (g > 0.3f) ? a : 0.0f;
        s_wneg[tid] = (g < -0.3f) ? a : 0.0f;
    }
    __syncthreads();
    if (tid == 0) {
        float sp = 0.f, sn = 0.f;
#pragma unroll
        for (int t = 0; t < TOPK; t++) { sp += s_wpos[t]; sn += s_wneg[t]; }
        s_inv[0] = 1.0f / (sp + 1e-8f);
        s_inv[1] = 1.0f / (sn + 1e-8f);
    }
    __syncthreads();

    // ---- message aggregation into smem (+ load h) ----
    if (tid < 64) {
        int d = tid;
        float acc = 0.f;
#pragma unroll
        for (int t = 0; t < TOPK; t++)
            acc = fmaf(s_wpos[t], g_msgpos[(size_t)s_topi[t] * DD + d], acc);
        s_mpos[d] = acc * s_inv[0];
    } else if (tid < 128) {
        int d = tid - 64;
        float acc = 0.f;
#pragma unroll
        for (int t = 0; t < TOPK; t++)
            acc = fmaf(s_wneg[t], g_msgneg[(size_t)s_topi[t] * DD + d], acc);
        s_mneg[d] = acc * s_inv[1];
    } else if (tid < 192) {
        int d = tid - 128;
        s_hh[d] = g_h[(size_t)i * DD + d];
    }
    __syncthreads();

    // ---- GRU gate dot-products: 4 groups x 64 d, transposed weights ----
    {
        int d = tid & 63;
        int grp = tid >> 6;
        float a0 = 0.f, a1 = 0.f, a2 = 0.f;
        const float* wT = (grp == 0) ? g_wTip : (grp == 1) ? g_wThp
                        : (grp == 2) ? g_wTin : g_wThn;
        const float* vec = (grp == 0) ? s_mpos : (grp == 1) ? s_hh
                         : (grp == 2) ? s_mneg : s_hh;
#pragma unroll 8
        for (int f = 0; f < DD; f++) {
            float xv = vec[f];
            const float* wr = wT + f * 192;
            a0 = fmaf(xv, wr[d], a0);
            a1 = fmaf(xv, wr[64 + d], a1);
            a2 = fmaf(xv, wr[128 + d], a2);
        }
        float* dst = (grp == 0) ? &s_gp[0][0] : (grp == 1) ? &s_gp[3][0]
                   : (grp == 2) ? &s_gn[0][0] : &s_gn[3][0];
        dst[0 * DD + d] = a0;
        dst[1 * DD + d] = a1;
        dst[2 * DD + d] = a2;
    }
    __syncthreads();

    // ---- GRU nonlinearities ----
    if (tid < 64) {
        int d = tid;
        float r = sigmoidf_((s_gp[0][d] + bih_p[d]) + (s_gp[3][d] + bhh_p[d]));
        float z = sigmoidf_((s_gp[1][d] + bih_p[64 + d]) + (s_gp[4][d] + bhh_p[64 + d]));
        float n2 = tanhf((s_gp[2][d] + bih_p[128 + d]) + r * (s_gp[5][d] + bhh_p[128 + d]));
        s_hp[d] = (1.0f - z) * n2 + z * s_hh[d];
    } else if (tid < 128) {
        int d = tid - 64;
        float r = sigmoidf_((s_gn[0][d] + bih_n[d]) + (s_gn[3][d] + bhh_n[d]));
        float z = sigmoidf_((s_gn[1][d] + bih_n[64 + d]) + (s_gn[4][d] + bhh_n[64 + d]));
        float n2 = tanhf((s_gn[2][d] + bih_n[128 + d]) + r * (s_gn[5][d] + bhh_n[128 + d]));
        s_hn[d] = (1.0f - z) * n2 + z * s_hh[d];
    }
    __syncthreads();

    // ---- combine: out = [h_pos, h_neg] @ comb_w + comb_b ----
    if (tid < 64) {
        int d = tid;
        float acc = comb_b[d];
#pragma unroll 8
        for (int kk = 0; kk < DD; kk++) {
            acc = fmaf(s_hp[kk], comb_w[kk * DD + d], acc);
            acc = fmaf(s_hn[kk], comb_w[(DD + kk) * DD + d], acc);
        }
        out[(size_t)i * DD + d] = acc;
    }
}

// ---------------- launch ---------------------------------------------------
extern "C" void kernel_launch(void* const* d_in, const int* in_sizes, int n_in,
                              void* d_out, int out_size)
{
    const float* x_risk   = (const float*)d_in[0];
    const float* mfg      = (const float*)d_in[1];
    const float* enc_w    = (const float*)d_in[2];
    const float* enc_b    = (const float*)d_in[3];
    const float* ln_g     = (const float*)d_in[4];
    const float* ln_b     = (const float*)d_in[5];
    const float* att_w1   = (const float*)d_in[6];
    const float* att_b1   = (const float*)d_in[7];
    const float* att_w2   = (const float*)d_in[8];
    const float* att_b2   = (const float*)d_in[9];
    const float* msg_pos_w = (const float*)d_in[10];
    const float* msg_pos_b = (const float*)d_in[11];
    const float* gru_pos_wih = (const float*)d_in[12];
    const float* gru_pos_whh = (const float*)d_in[13];
    const float* gru_pos_bih = (const float*)d_in[14];
    const float* gru_pos_bhh = (const float*)d_in[15];
    const float* msg_neg_w = (const float*)d_in[16];
    const float* msg_neg_b = (const float*)d_in[17];
    const float* gru_neg_wih = (const float*)d_in[18];
    const float* gru_neg_whh = (const float*)d_in[19];
    const float* gru_neg_bih = (const float*)d_in[20];
    const float* gru_neg_bhh = (const float*)d_in[21];
    const float* comb_w   = (const float*)d_in[22];
    const float* comb_b   = (const float*)d_in[23];
    float* out = (float*)d_out;

    // encode (blocks 0..NN-1) + GRU-weight transpose (blocks NN..NN+TRB-1)
    k_encode<<<NN + TRB, 64>>>(x_risk, enc_w, enc_b, ln_g, ln_b,
                               att_w1, att_b1, msg_pos_w, msg_pos_b,
                               msg_neg_w, msg_neg_b,
                               gru_pos_wih, gru_pos_whh,
                               gru_neg_wih, gru_neg_whh);

    dim3 gb((NN + 63) / 64, (NN + 63) / 64);
    dim3 tb(16, 16);
    k_att<<<gb, tb>>>(att_w2, att_b2);

    k_topk_gru<<<NN, 256>>>(mfg,
                            gru_pos_bih, gru_pos_bhh,
                            gru_neg_bih, gru_neg_bhh,
                            comb_w, comb_b, out);
}